// round 4
// baseline (speedup 1.0000x reference)
#include <cuda_runtime.h>
#include <math.h>

// Problem constants (fixed by the reference)
#define B_DIM 2
#define L_DIM 2048
#define V_DIM 32001
#define ROWS (B_DIM * L_DIM)
#define REV_FLOATS ((size_t)ROWS * V_DIM)        // 131076096, divisible by 4
#define REV_FLOAT4 (REV_FLOATS / 4)              // 32769024

__device__ __forceinline__ float gumbel_noise(float u) {
    const float GEPS = 1e-6f;
    return GEPS - logf(GEPS + (1.0f - GEPS) * u);
}

// Kernel A: flat 128B-aligned zero fill of the whole rev_rate region.
// Ignoring row structure keeps every warp's 512B store fully sector-aligned
// (the per-row version straddled 5 sectors per warp -> 1.25x traffic).
__global__ void zero_fill_kernel(float4* __restrict__ p, long long n4) {
    long long i = (long long)blockIdx.x * blockDim.x + threadIdx.x;
    const long long stride = (long long)gridDim.x * blockDim.x;
    const float4 z = make_float4(0.f, 0.f, 0.f, 0.f);
    for (; i < n4; i += stride) p[i] = z;
}

// Kernel B: row logic. 64 blocks stride over the 4096 rows.
//  - non-mask row: rev row is exactly zero (already zeroed); argmax is
//    deterministically x. Thread 0 writes x_new.
//  - mask row (~0-1 of 4096): full SEDD reverse-rate + gumbel-max sample,
//    overwriting the zeroed row.
__global__ void euler_row_kernel(const float* __restrict__ outp,   // [B,L,V]
                                 const int* __restrict__ xt,       // [B,L]
                                 const float* __restrict__ t,      // [B]
                                 const float* __restrict__ step_p, // [1]
                                 const float* __restrict__ u,      // [B,L,V]
                                 float* __restrict__ x_new,        // [B*L]
                                 float* __restrict__ rev)          // [B,L,V]
{
    const int tid = threadIdx.x;
    const int nthreads = blockDim.x;
    const int mask_tok = V_DIM - 1;

    for (int row = blockIdx.x; row < ROWS; row += gridDim.x) {
        int x = xt[row];
        if (x == -1) x = mask_tok;

        if (x != mask_tok) {
            if (tid == 0) x_new[row] = (float)x;
            continue;
        }

        // ---- mask row: heavy path ----
        const int b = row / L_DIM;
        const float EPS = 1e-3f;
        const float step = *step_p;
        const float sigma = (1.0f - EPS) / (1.0f - (1.0f - EPS) * t[b]);

        const float* __restrict__ orow = outp + (long long)row * V_DIM;
        const float* __restrict__ urow = u    + (long long)row * V_DIM;
        float* __restrict__       rrow = rev  + (long long)row * V_DIM;

        float sum = 0.0f;
        float best_v = -INFINITY;
        int   best_i = V_DIM;   // larger than any real index

        for (int v = tid; v < V_DIM; v += nthreads) {
            if (v == mask_tok) continue;
            float s = expf(orow[v]);
            sum += s;
            float r = sigma * s;          // rev_rate off-diagonal
            rrow[v] = r;
            float g = gumbel_noise(urow[v]);
            float ratio = (step * r) / g; // xt_prob[v] = 0 + step*rev
            if (ratio > best_v || (ratio == best_v && v < best_i)) {
                best_v = ratio;
                best_i = v;
            }
        }

        __shared__ float s_sum[256];
        __shared__ float s_val[256];
        __shared__ int   s_idx[256];
        s_sum[tid] = sum;
        s_val[tid] = best_v;
        s_idx[tid] = best_i;
        __syncthreads();

        for (int off = 128; off > 0; off >>= 1) {
            if (tid < off) {
                s_sum[tid] += s_sum[tid + off];
                float ov = s_val[tid + off];
                int   oi = s_idx[tid + off];
                if (ov > s_val[tid] || (ov == s_val[tid] && oi < s_idx[tid])) {
                    s_val[tid] = ov;
                    s_idx[tid] = oi;
                }
            }
            __syncthreads();
        }

        if (tid == 0) {
            float total = s_sum[0];
            float rd = sigma * (-total);           // diagonal rev_rate
            rrow[mask_tok] = rd;
            float prob = 1.0f + step * rd;         // oh=1 at diagonal
            float g = gumbel_noise(urow[mask_tok]);
            float ratio = prob / g;
            int res = s_idx[0];
            float bv = s_val[0];
            // diagonal index is V-1 (largest), so on tie the off-diag wins
            if (ratio > bv) res = mask_tok;
            x_new[row] = (res == mask_tok) ? -1.0f : (float)res;
        }
        __syncthreads();   // reuse of shared arrays on next masked row
    }
}

extern "C" void kernel_launch(void* const* d_in, const int* in_sizes, int n_in,
                              void* d_out, int out_size) {
    const float* outp   = (const float*)d_in[0]; // [B,L,V] f32
    const int*   xt     = (const int*)  d_in[1]; // [B,L]   i32
    const float* t      = (const float*)d_in[2]; // [B]     f32
    const float* step_p = (const float*)d_in[3]; // scalar  f32
    const float* u      = (const float*)d_in[4]; // [B,L,V] f32

    float* x_new = (float*)d_out;                  // first B*L elements
    float* rev   = (float*)d_out + ROWS;           // then B*L*V elements

    // Flat, alignment-preserving zero of the rev region (the compulsory
    // 524 MB write). 4096 blocks x 256 threads, grid-stride float4.
    zero_fill_kernel<<<4096, 256>>>((float4*)rev, (long long)REV_FLOAT4);

    // Tiny logic kernel: x_new for all rows, heavy path only for mask rows.
    euler_row_kernel<<<64, 256>>>(outp, xt, t, step_p, u, x_new, rev);
}

// round 5
// speedup vs baseline: 1.3869x; 1.3869x over previous
#include <cuda_runtime.h>
#include <math.h>

// Problem constants (fixed by the reference)
#define B_DIM 2
#define L_DIM 2048
#define V_DIM 32001
#define ROWS (B_DIM * L_DIM)          // 4096 = 16 blocks x 256 threads

__device__ __forceinline__ float gumbel_noise(float u) {
    const float GEPS = 1e-6f;
    return GEPS - logf(GEPS + (1.0f - GEPS) * u);
}

// Thread-per-row logic kernel (grid 16 x 256 = exactly ROWS threads).
//  - non-mask row (essentially all): rev row is exactly zero (memset already
//    wrote it); the gumbel argmax is deterministically x. One coalesced read
//    of xt + one coalesced write of x_new.
//  - mask row (~0-1 expected of 4096): collected into a per-block shared
//    worklist; the whole block then cooperates on the SEDD reverse-rate +
//    gumbel-max sample, overwriting the zeroed row.
__global__ void row_logic_kernel(const float* __restrict__ outp,   // [B,L,V]
                                 const int* __restrict__ xt,       // [B,L]
                                 const float* __restrict__ t,      // [B]
                                 const float* __restrict__ step_p, // [1]
                                 const float* __restrict__ u,      // [B,L,V]
                                 float* __restrict__ x_new,        // [B*L]
                                 float* __restrict__ rev)          // [B,L,V]
{
    const int tid = threadIdx.x;
    const int row = blockIdx.x * blockDim.x + tid;   // 0..4095
    const int mask_tok = V_DIM - 1;

    __shared__ int s_count;
    __shared__ int s_rows[256];

    if (tid == 0) s_count = 0;
    __syncthreads();

    int x = xt[row];
    if (x == -1) x = mask_tok;

    if (x != mask_tok) {
        x_new[row] = (float)x;      // coalesced fast path
    } else {
        int slot = atomicAdd(&s_count, 1);
        s_rows[slot] = row;
    }
    __syncthreads();

    const int cnt = s_count;
    if (cnt == 0) return;           // common case: whole block done

    // ---- cooperative heavy path for each masked row in this block ----
    __shared__ float s_sum[256];
    __shared__ float s_val[256];
    __shared__ int   s_idx[256];

    const float EPS  = 1e-3f;
    const float step = *step_p;

    for (int m = 0; m < cnt; m++) {
        const int mrow = s_rows[m];
        const int b = mrow / L_DIM;
        const float sigma = (1.0f - EPS) / (1.0f - (1.0f - EPS) * t[b]);

        const float* __restrict__ orow = outp + (long long)mrow * V_DIM;
        const float* __restrict__ urow = u    + (long long)mrow * V_DIM;
        float* __restrict__       rrow = rev  + (long long)mrow * V_DIM;

        float sum = 0.0f;
        float best_v = -INFINITY;
        int   best_i = V_DIM;   // larger than any real index

        for (int v = tid; v < V_DIM; v += 256) {
            if (v == mask_tok) continue;
            float s = expf(orow[v]);
            sum += s;
            float r = sigma * s;          // rev_rate off-diagonal
            rrow[v] = r;
            float g = gumbel_noise(urow[v]);
            float ratio = (step * r) / g; // xt_prob[v] = 0 + step*rev
            if (ratio > best_v || (ratio == best_v && v < best_i)) {
                best_v = ratio;
                best_i = v;
            }
        }

        s_sum[tid] = sum;
        s_val[tid] = best_v;
        s_idx[tid] = best_i;
        __syncthreads();

        for (int off = 128; off > 0; off >>= 1) {
            if (tid < off) {
                s_sum[tid] += s_sum[tid + off];
                float ov = s_val[tid + off];
                int   oi = s_idx[tid + off];
                if (ov > s_val[tid] || (ov == s_val[tid] && oi < s_idx[tid])) {
                    s_val[tid] = ov;
                    s_idx[tid] = oi;
                }
            }
            __syncthreads();
        }

        if (tid == 0) {
            float total = s_sum[0];
            float rd = sigma * (-total);           // diagonal rev_rate
            rrow[mask_tok] = rd;
            float prob = 1.0f + step * rd;         // oh=1 at diagonal
            float g = gumbel_noise(urow[mask_tok]);
            float ratio = prob / g;
            int res = s_idx[0];
            float bv = s_val[0];
            // diagonal index is V-1 (largest), so on a tie off-diagonal wins
            if (ratio > bv) res = mask_tok;
            x_new[mrow] = (res == mask_tok) ? -1.0f : (float)res;
        }
        __syncthreads();
    }
}

extern "C" void kernel_launch(void* const* d_in, const int* in_sizes, int n_in,
                              void* d_out, int out_size) {
    const float* outp   = (const float*)d_in[0]; // [B,L,V] f32
    const int*   xt     = (const int*)  d_in[1]; // [B,L]   i32
    const float* t      = (const float*)d_in[2]; // [B]     f32
    const float* step_p = (const float*)d_in[3]; // scalar  f32
    const float* u      = (const float*)d_in[4]; // [B,L,V] f32

    float* x_new = (float*)d_out;                  // first B*L elements
    float* rev   = (float*)d_out + ROWS;           // then B*L*V elements

    // Compulsory 524 MB zero of rev_rate at the HBM write ceiling (~7.4 TB/s).
    cudaMemsetAsync(rev, 0, (size_t)ROWS * V_DIM * sizeof(float));

    // Tiny thread-per-row logic pass (16 KB read + 16 KB write + rare heavy rows).
    row_logic_kernel<<<ROWS / 256, 256>>>(outp, xt, t, step_p, u, x_new, rev);
}